// round 10
// baseline (speedup 1.0000x reference)
#include <cuda_runtime.h>
#include <cuda_fp16.h>
#include <cstdint>

#define PB 2
#define PH 12
#define PT 2048
#define PD 64
#define PR 16
#define PD_STD 48
#define PBH (PB * PH)
#define QT 64
#define KT 128
#define LOG2E 1.4426950408889634f

// smem byte offsets (attn)
#define SQ  0          // Q tile 64x128B   = 8192
#define SK0 8192       // K tile 128x128B  = 16384
#define SK1 24576
#define SV0 40960      // V tile 128x128B  = 16384
#define SV1 57344
#define SB0 73728      // bias 128 f32 = 512
#define SB1 74240
#define SMEM_BYTES 74752

__device__ __half g_Qh[PBH * PT * PD];
__device__ __half g_Kh[PBH * PT * PD];
__device__ __half g_Vh[PBH * PT * PD];
__device__ float  g_bw[PBH * PT];

__device__ __forceinline__ void mma16816(float& d0, float& d1, float& d2, float& d3,
                                         unsigned a0, unsigned a1, unsigned a2, unsigned a3,
                                         unsigned b0, unsigned b1) {
    asm volatile(
        "mma.sync.aligned.m16n8k16.row.col.f32.f16.f16.f32 "
        "{%0,%1,%2,%3},{%4,%5,%6,%7},{%8,%9},{%0,%1,%2,%3};"
        : "+f"(d0), "+f"(d1), "+f"(d2), "+f"(d3)
        : "r"(a0), "r"(a1), "r"(a2), "r"(a3), "r"(b0), "r"(b1));
}
__device__ __forceinline__ void ldsm4(unsigned& r0, unsigned& r1, unsigned& r2, unsigned& r3,
                                      unsigned addr) {
    asm volatile("ldmatrix.sync.aligned.m8n8.x4.shared.b16 {%0,%1,%2,%3}, [%4];"
                 : "=r"(r0), "=r"(r1), "=r"(r2), "=r"(r3) : "r"(addr));
}
__device__ __forceinline__ void ldsm4t(unsigned& r0, unsigned& r1, unsigned& r2, unsigned& r3,
                                       unsigned addr) {
    asm volatile("ldmatrix.sync.aligned.m8n8.x4.trans.shared.b16 {%0,%1,%2,%3}, [%4];"
                 : "=r"(r0), "=r"(r1), "=r"(r2), "=r"(r3) : "r"(addr));
}
__device__ __forceinline__ void cpa16(unsigned dst, const void* src) {
    asm volatile("cp.async.cg.shared.global [%0], [%1], 16;" :: "r"(dst), "l"(src));
}
__device__ __forceinline__ float ex2(float x) {
    float y; asm("ex2.approx.ftz.f32 %0, %1;" : "=f"(y) : "f"(x)); return y;
}
// packed fp16 exp2: f32 subtract (precision), half2 pack, MUFU f16x2
__device__ __forceinline__ unsigned ex2_pk(float x0, float x1) {
    const __half2 h = __floats2half2_rn(x0, x1);
    unsigned y;
    asm("ex2.approx.f16x2 %0, %1;" : "=r"(y) : "r"(*reinterpret_cast<const unsigned*>(&h)));
    return y;
}

// ---------------------------------------------------------------------------
// Fused prologue (unchanged): fp16 Q_aug (0.125*log2e folded), fp16 K_aug,
// fp16 V, pre-weighted bias. Block = 64 t-rows of one head.
// ---------------------------------------------------------------------------
#define AP 68
__global__ __launch_bounds__(256) void aug_kernel(
    const float* __restrict__ Q, const float* __restrict__ K,
    const float* __restrict__ V, const float* __restrict__ d_bias,
    const float* __restrict__ W,
    const float* __restrict__ w_std, const float* __restrict__ w_rec,
    const float* __restrict__ w_disc)
{
    __shared__ float sW[PD * PR];
    __shared__ float sQ[64 * AP];
    __shared__ float sK[64 * AP];
    __shared__ float sLQ[64 * 16];
    __shared__ float sLK[64 * 16];

    const int tid = threadIdx.x;
    const int bh  = blockIdx.y;
    const int h   = bh % PH;
    const int t0  = blockIdx.x * 64;
    const size_t gbase = ((size_t)bh * PT + t0) * PD;

    for (int i = tid; i < PD * PR / 4; i += 256)
        *reinterpret_cast<float4*>(&sW[i * 4]) =
            reinterpret_cast<const float4*>(W)[i];
#pragma unroll
    for (int k = 0; k < 4; k++) {
        const int i = tid + k * 256;
        const int r = i >> 4, c4 = (i & 15) * 4;
        *reinterpret_cast<float4*>(&sQ[r * AP + c4]) =
            reinterpret_cast<const float4*>(Q + gbase)[i];
        *reinterpret_cast<float4*>(&sK[r * AP + c4]) =
            reinterpret_cast<const float4*>(K + gbase)[i];
    }
    __syncthreads();

    {
        const int r = tid >> 2, c4 = (tid & 3) * 4;
        float aq0 = 0.f, aq1 = 0.f, aq2 = 0.f, aq3 = 0.f;
        float ak0 = 0.f, ak1 = 0.f, ak2 = 0.f, ak3 = 0.f;
#pragma unroll
        for (int j = 0; j < PD; j++) {
            const float qv = sQ[r * AP + j];
            const float kv = sK[r * AP + j];
            const float4 wv = *reinterpret_cast<const float4*>(&sW[j * PR + c4]);
            aq0 = fmaf(qv, wv.x, aq0); aq1 = fmaf(qv, wv.y, aq1);
            aq2 = fmaf(qv, wv.z, aq2); aq3 = fmaf(qv, wv.w, aq3);
            ak0 = fmaf(kv, wv.x, ak0); ak1 = fmaf(kv, wv.y, ak1);
            ak2 = fmaf(kv, wv.z, ak2); ak3 = fmaf(kv, wv.w, ak3);
        }
        *reinterpret_cast<float4*>(&sLQ[r * 16 + c4]) = make_float4(aq0, aq1, aq2, aq3);
        *reinterpret_cast<float4*>(&sLK[r * 16 + c4]) = make_float4(ak0, ak1, ak2, ak3);
    }
    __syncthreads();

    {
        const float sstd = sqrtf(w_std[h]);
        const float srec = sqrtf(w_rec[h]);
        const float SCL = 0.125f * LOG2E;
        const int r = tid >> 2, d0 = (tid & 3) * 16;
        const size_t grow = gbase + (size_t)r * PD + d0;

        __half2 qo[8], ko[8], vo[8];
#pragma unroll
        for (int j = 0; j < 8; j++) {
            const int d = d0 + 2 * j;
            float q0, q1, k0, k1;
            if (d < PD_STD) {
                q0 = SCL * sstd * sQ[r * AP + d];   q1 = SCL * sstd * sQ[r * AP + d + 1];
                k0 = sstd * sK[r * AP + d];         k1 = sstd * sK[r * AP + d + 1];
            } else {
                const int rr = d - PD_STD;
                q0 = SCL * srec * sLK[r * 16 + rr]; q1 = SCL * srec * sLK[r * 16 + rr + 1];
                k0 = srec * sLQ[r * 16 + rr];       k1 = srec * sLQ[r * 16 + rr + 1];
            }
            qo[j] = __floats2half2_rn(q0, q1);
            ko[j] = __floats2half2_rn(k0, k1);
        }
#pragma unroll
        for (int j4 = 0; j4 < 4; j4++) {
            const float4 vv = *reinterpret_cast<const float4*>(&V[grow + 4 * j4]);
            vo[2 * j4]     = __floats2half2_rn(vv.x, vv.y);
            vo[2 * j4 + 1] = __floats2half2_rn(vv.z, vv.w);
        }
        *reinterpret_cast<uint4*>(&g_Qh[grow])     = *reinterpret_cast<uint4*>(&qo[0]);
        *reinterpret_cast<uint4*>(&g_Qh[grow + 8]) = *reinterpret_cast<uint4*>(&qo[4]);
        *reinterpret_cast<uint4*>(&g_Kh[grow])     = *reinterpret_cast<uint4*>(&ko[0]);
        *reinterpret_cast<uint4*>(&g_Kh[grow + 8]) = *reinterpret_cast<uint4*>(&ko[4]);
        *reinterpret_cast<uint4*>(&g_Vh[grow])     = *reinterpret_cast<uint4*>(&vo[0]);
        *reinterpret_cast<uint4*>(&g_Vh[grow + 8]) = *reinterpret_cast<uint4*>(&vo[4]);
        if (tid < 64)
            g_bw[(size_t)bh * PT + t0 + tid] =
                LOG2E * w_disc[h] * d_bias[(size_t)bh * PT + t0 + tid];
    }
}

// ---------------------------------------------------------------------------
// 128-key stage loader (SW128 xor swizzle) + f32 bias.
// ---------------------------------------------------------------------------
__device__ __forceinline__ void load_stage(unsigned sb, int stage,
                                           const __half* Kt, const __half* Vt,
                                           const float* bt, int tid)
{
    const unsigned kb = sb + (stage ? SK1 : SK0);
    const unsigned vb = sb + (stage ? SV1 : SV0);
    const unsigned bb = sb + (stage ? SB1 : SB0);
#pragma unroll
    for (int i = 0; i < 8; i++) {
        const int ch = tid + i * 128;
        const int r = ch >> 3, a = ch & 7;
        const unsigned off = (unsigned)(r * 128 + ((a ^ (r & 7)) << 4));
        cpa16(kb + off, Kt + r * 64 + a * 8);
        cpa16(vb + off, Vt + r * 64 + a * 8);
    }
    if (tid < 32) cpa16(bb + (unsigned)tid * 16u, bt + tid * 4);
    asm volatile("cp.async.commit_group;");
}

// ---------------------------------------------------------------------------
// Flash attention: HMMA.16816, 128-key tiles, explicit distance-2 ldsm
// software pipeline, hoisted swizzle addressing, fp16-packed exp spread
// across PV steps, row-sums via ones-column MMA. 128 threads, 3 CTA/SM.
// ---------------------------------------------------------------------------
__global__ __launch_bounds__(128, 3) void attn_kernel(float* __restrict__ out)
{
    extern __shared__ char sm[];
    const unsigned sb = (unsigned)__cvta_generic_to_shared(sm);

    const int bh = blockIdx.y;
    const int q_tile = (PT / QT - 1) - blockIdx.x;   // heavy tiles first
    const int nkt = q_tile / 2 + 1;                  // 128-key tiles
    const size_t base = (size_t)bh * PT * PD;
    const __half* Kg = g_Kh + base;
    const __half* Vg = g_Vh + base;
    const float*  bg = g_bw + (size_t)bh * PT;

    const int tid = threadIdx.x;
    const int w = tid >> 5, lane = tid & 31;
    const int g = lane >> 2, c = lane & 3;

    // fragment row/atom components
    const int kr  = 8 * (lane >> 4) + (lane & 7);                 // K rows (B frag)
    const int kao = (lane >> 3) & 1;
    const int qr  = 16 * w + 8 * ((lane >> 3) & 1) + (lane & 7);  // Q rows (A frag)
    const int qao = lane >> 4;
    const int vro = 8 * ((lane >> 3) & 1) + (lane & 7);           // V rows (trans B)
    const int vao = lane >> 4;
    const int qsw = qr & 7, ksw = kr & 7, vsw = vro & 7;
    const int grow0 = q_tile * QT + 16 * w + g;      // this lane's first q row

    // loop-invariant swizzled column offsets (hoisted out of volatile stream)
    unsigned colK[4], colQ[4], colV[4];
#pragma unroll
    for (int kk = 0; kk < 4; kk++) {
        colK[kk] = (unsigned)(((2 * kk + kao) ^ ksw) << 4);
        colQ[kk] = (unsigned)(((2 * kk + qao) ^ qsw) << 4);
        colV[kk] = (unsigned)(((2 * kk + vao) ^ vsw) << 4);
    }
    const unsigned qbase2 = sb + SQ + (unsigned)qr * 128u;

    // stage0 K/V/bias + Q tile
    load_stage(sb, 0, Kg, Vg, bg, tid);
    {
        const __half* Qt = g_Qh + base + (size_t)q_tile * QT * PD;
#pragma unroll
        for (int i = 0; i < 4; i++) {
            const int ch = tid + i * 128;
            const int r = ch >> 3, a = ch & 7;
            cpa16(sb + SQ + (unsigned)(r * 128 + ((a ^ (r & 7)) << 4)), Qt + r * 64 + a * 8);
        }
        asm volatile("cp.async.commit_group;");
    }
    asm volatile("cp.async.wait_group 0;");
    __syncthreads();

    float acc[8][4];
#pragma unroll
    for (int nb = 0; nb < 8; nb++)
#pragma unroll
        for (int j = 0; j < 4; j++) acc[nb][j] = 0.f;
    float accl[4] = {0.f, 0.f, 0.f, 0.f};            // P row sums (ones-column mma)
    float m0 = -1e30f, m1 = -1e30f;

    int stage = 0;
    for (int kt = 0; kt < nkt; kt++) {
        if (kt) {
            asm volatile("cp.async.wait_group 0;");
            __syncthreads();
        }
        if (kt + 1 < nkt)
            load_stage(sb, stage ^ 1, Kg + (size_t)(kt + 1) * KT * PD,
                       Vg + (size_t)(kt + 1) * KT * PD, bg + (kt + 1) * KT, tid);

        const unsigned kb2 = sb + (stage ? SK1 : SK0) + (unsigned)kr * 128u;
        const unsigned vb2 = sb + (stage ? SV1 : SV0) + (unsigned)vro * 128u;
        const float* sB = (const float*)(sm + (stage ? SB1 : SB0));

        // ---- S (16x128 per warp): C-init = pre-weighted bias ----
        float s[16][4];
#pragma unroll
        for (int nb = 0; nb < 16; nb++) {
            const float2 bb = *reinterpret_cast<const float2*>(sB + 8 * nb + 2 * c);
            s[nb][0] = bb.x; s[nb][1] = bb.y;
            s[nb][2] = bb.x; s[nb][3] = bb.y;
        }

        // flattened 32-step (ldsm -> 2 mma) stream, distance-2 K ring,
        // Q fragments for kk loaded one kk ahead (parity buffer)
        {
            unsigned ring[3][4];
            unsigned qfb[2][4];
            ldsm4(qfb[0][0], qfb[0][1], qfb[0][2], qfb[0][3], qbase2 + colQ[0]);
            ldsm4(ring[0][0], ring[0][1], ring[0][2], ring[0][3], kb2 + colK[0]);
            ldsm4(ring[1][0], ring[1][1], ring[1][2], ring[1][3], kb2 + colK[0] + 2048u);
#pragma unroll
            for (int kk = 0; kk < 4; kk++) {
#pragma unroll
                for (int A2 = 0; A2 < 8; A2++) {
                    const int idx = kk * 8 + A2;
                    if (idx + 2 < 32) {
                        const int pkk = (idx + 2) >> 3, pA2 = (idx + 2) & 7;
                        unsigned* d = ring[(idx + 2) % 3];
                        ldsm4(d[0], d[1], d[2], d[3],
                              kb2 + colK[pkk] + (unsigned)(pA2 * 2048));
                    }
                    if (A2 == 4 && kk < 3) {
                        unsigned* qd = qfb[(kk + 1) & 1];
                        ldsm4(qd[0], qd[1], qd[2], qd[3], qbase2 + colQ[kk + 1]);
                    }
                    const unsigned* b = ring[idx % 3];
                    const unsigned* qa = qfb[kk & 1];
                    mma16816(s[2*A2][0], s[2*A2][1], s[2*A2][2], s[2*A2][3],
                             qa[0], qa[1], qa[2], qa[3], b[0], b[1]);
                    mma16816(s[2*A2+1][0], s[2*A2+1][1], s[2*A2+1][2], s[2*A2+1][3],
                             qa[0], qa[1], qa[2], qa[3], b[2], b[3]);
                }
            }
        }

        if (kt == nkt - 1) {   // causal mask, last 128-key tile
            const int kk0 = grow0 - kt * KT;
#pragma unroll
            for (int nb = 0; nb < 16; nb++) {
                const int j0 = 8 * nb + 2 * c, j1 = j0 + 1;
                if (j0 > kk0)     s[nb][0] = -1e30f;
                if (j1 > kk0)     s[nb][1] = -1e30f;
                if (j0 > kk0 + 8) s[nb][2] = -1e30f;
                if (j1 > kk0 + 8) s[nb][3] = -1e30f;
            }
        }

        // ---- row max over 128 keys (f32) ----
        float rm0 = fmaxf(s[0][0], s[0][1]), rm1 = fmaxf(s[0][2], s[0][3]);
#pragma unroll
        for (int nb = 1; nb < 16; nb++) {
            rm0 = fmaxf(rm0, fmaxf(s[nb][0], s[nb][1]));
            rm1 = fmaxf(rm1, fmaxf(s[nb][2], s[nb][3]));
        }
        rm0 = fmaxf(rm0, __shfl_xor_sync(0xffffffffu, rm0, 1));
        rm0 = fmaxf(rm0, __shfl_xor_sync(0xffffffffu, rm0, 2));
        rm1 = fmaxf(rm1, __shfl_xor_sync(0xffffffffu, rm1, 1));
        rm1 = fmaxf(rm1, __shfl_xor_sync(0xffffffffu, rm1, 2));
        const float mn0 = fmaxf(m0, rm0), mn1 = fmaxf(m1, rm1);
        const float co0 = ex2(m0 - mn0), co1 = ex2(m1 - mn1);
        const bool moved = (mn0 > m0) | (mn1 > m1);
        m0 = mn0; m1 = mn1;

        if (__ballot_sync(0xffffffffu, moved)) {     // skip rescale when max stable
#pragma unroll
            for (int nb = 0; nb < 8; nb++) {
                acc[nb][0] *= co0; acc[nb][1] *= co0;
                acc[nb][2] *= co1; acc[nb][3] *= co1;
            }
            accl[0] *= co0; accl[1] *= co0;
            accl[2] *= co1; accl[3] *= co1;
        }

        // ---- PV: flattened 32-step stream, distance-2 V ring, exp for kk+1
        //      spread across kk's steps, ones-column row-sum mma per kk ----
        {
            const unsigned ONES = 0x3C003C00u;
            unsigned ring[3][4];
            unsigned af[2][4];
            af[0][0] = ex2_pk(s[0][0] - mn0, s[0][1] - mn0);
            af[0][1] = ex2_pk(s[0][2] - mn1, s[0][3] - mn1);
            af[0][2] = ex2_pk(s[1][0] - mn0, s[1][1] - mn0);
            af[0][3] = ex2_pk(s[1][2] - mn1, s[1][3] - mn1);
            ldsm4t(ring[0][0], ring[0][1], ring[0][2], ring[0][3], vb2 + colV[0]);
            ldsm4t(ring[1][0], ring[1][1], ring[1][2], ring[1][3], vb2 + colV[1]);
#pragma unroll
            for (int kk = 0; kk < 8; kk++) {
#pragma unroll
                for (int A2 = 0; A2 < 4; A2++) {
                    const int idx = kk * 4 + A2;
                    if (idx + 2 < 32) {
                        const int pkk = (idx + 2) >> 2, pA2 = (idx + 2) & 3;
                        unsigned* d = ring[(idx + 2) % 3];
                        ldsm4t(d[0], d[1], d[2], d[3],
                               vb2 + (unsigned)(pkk * 2048) + colV[pA2]);
                    }
                    if (kk < 7) {   // one exp component per step for kk+1
                        unsigned* an = af[(kk + 1) & 1];
                        if (A2 == 0) an[0] = ex2_pk(s[2*kk+2][0] - mn0, s[2*kk+2][1] - mn0);
                        if (A2 == 1) an[1] = ex2_pk(s[2*kk+2][2] - mn1, s[2*kk+2][3] - mn1);
                        if (A2 == 2) an[2] = ex2_pk(s[2*kk+3][0] - mn0, s[2*kk+3][1] - mn0);
                        if (A2 == 3) an[3] = ex2_pk(s[2*kk+3][2] - mn1, s[2*kk+3][3] - mn1);
                    }
                    const unsigned* b = ring[idx % 3];
                    const unsigned* aa = af[kk & 1];
                    mma16816(acc[2*A2][0], acc[2*A2][1], acc[2*A2][2], acc[2*A2][3],
                             aa[0], aa[1], aa[2], aa[3], b[0], b[1]);
                    mma16816(acc[2*A2+1][0], acc[2*A2+1][1], acc[2*A2+1][2], acc[2*A2+1][3],
                             aa[0], aa[1], aa[2], aa[3], b[2], b[3]);
                }
                const unsigned* aa = af[kk & 1];
                mma16816(accl[0], accl[1], accl[2], accl[3],
                         aa[0], aa[1], aa[2], aa[3], ONES, ONES);
            }
        }
        stage ^= 1;
    }

    // ---- normalize + write (accl[0]=row g sum, accl[2]=row g+8 sum) ----
    const float inv0 = 1.0f / accl[0], inv1 = 1.0f / accl[2];
    float* og = out + base + ((size_t)q_tile * QT + 16 * w) * PD;
#pragma unroll
    for (int nb = 0; nb < 8; nb++) {
        *reinterpret_cast<float2*>(og + g * 64 + 8 * nb + 2 * c) =
            make_float2(acc[nb][0] * inv0, acc[nb][1] * inv0);
        *reinterpret_cast<float2*>(og + (g + 8) * 64 + 8 * nb + 2 * c) =
            make_float2(acc[nb][2] * inv1, acc[nb][3] * inv1);
    }
}

// ---------------------------------------------------------------------------
extern "C" void kernel_launch(void* const* d_in, const int* in_sizes, int n_in,
                              void* d_out, int out_size)
{
    const float* Q      = (const float*)d_in[0];
    const float* K      = (const float*)d_in[1];
    const float* V      = (const float*)d_in[2];
    const float* d_bias = (const float*)d_in[3];
    const float* W      = (const float*)d_in[4];
    const float* w_std  = (const float*)d_in[5];
    const float* w_rec  = (const float*)d_in[6];
    const float* w_disc = (const float*)d_in[7];
    float* out = (float*)d_out;

    cudaFuncSetAttribute(attn_kernel, cudaFuncAttributeMaxDynamicSharedMemorySize,
                         SMEM_BYTES);

    dim3 ag(PT / 64, PBH);
    aug_kernel<<<ag, 256>>>(Q, K, V, d_bias, W, w_std, w_rec, w_disc);

    dim3 grid(PT / QT, PBH);
    attn_kernel<<<grid, 128, SMEM_BYTES>>>(out);
}

// round 11
// speedup vs baseline: 1.0068x; 1.0068x over previous
#include <cuda_runtime.h>
#include <cuda_fp16.h>
#include <cstdint>

#define PB 2
#define PH 12
#define PT 2048
#define PD 64
#define PR 16
#define PD_STD 48
#define PBH (PB * PH)
#define QT 64
#define KT 128
#define LOG2E 1.4426950408889634f

// smem byte offsets (attn)
#define SQ  0          // Q tile 64x128B   = 8192
#define SK0 8192       // K tile 128x128B  = 16384
#define SK1 24576
#define SV0 40960      // V tile 128x128B  = 16384
#define SV1 57344
#define SB0 73728      // bias 128 f32 = 512
#define SB1 74240
#define SMEM_BYTES 74752

__device__ __half g_Qh[PBH * PT * PD];
__device__ __half g_Kh[PBH * PT * PD];
__device__ __half g_Vh[PBH * PT * PD];
__device__ float  g_bw[PBH * PT];

__device__ __forceinline__ void mma16816(float& d0, float& d1, float& d2, float& d3,
                                         unsigned a0, unsigned a1, unsigned a2, unsigned a3,
                                         unsigned b0, unsigned b1) {
    asm volatile(
        "mma.sync.aligned.m16n8k16.row.col.f32.f16.f16.f32 "
        "{%0,%1,%2,%3},{%4,%5,%6,%7},{%8,%9},{%0,%1,%2,%3};"
        : "+f"(d0), "+f"(d1), "+f"(d2), "+f"(d3)
        : "r"(a0), "r"(a1), "r"(a2), "r"(a3), "r"(b0), "r"(b1));
}
// first-mma form: C operand = {c0,c1,c0,c1} (rank-1 bias, col-only), D pure out
__device__ __forceinline__ void mma16816_init(float& d0, float& d1, float& d2, float& d3,
                                              unsigned a0, unsigned a1, unsigned a2, unsigned a3,
                                              unsigned b0, unsigned b1, float c0, float c1) {
    asm volatile(
        "mma.sync.aligned.m16n8k16.row.col.f32.f16.f16.f32 "
        "{%0,%1,%2,%3},{%4,%5,%6,%7},{%8,%9},{%10,%11,%10,%11};"
        : "=f"(d0), "=f"(d1), "=f"(d2), "=f"(d3)
        : "r"(a0), "r"(a1), "r"(a2), "r"(a3), "r"(b0), "r"(b1),
          "f"(c0), "f"(c1));
}
__device__ __forceinline__ void ldsm4(unsigned& r0, unsigned& r1, unsigned& r2, unsigned& r3,
                                      unsigned addr) {
    asm volatile("ldmatrix.sync.aligned.m8n8.x4.shared.b16 {%0,%1,%2,%3}, [%4];"
                 : "=r"(r0), "=r"(r1), "=r"(r2), "=r"(r3) : "r"(addr));
}
__device__ __forceinline__ void ldsm4t(unsigned& r0, unsigned& r1, unsigned& r2, unsigned& r3,
                                       unsigned addr) {
    asm volatile("ldmatrix.sync.aligned.m8n8.x4.trans.shared.b16 {%0,%1,%2,%3}, [%4];"
                 : "=r"(r0), "=r"(r1), "=r"(r2), "=r"(r3) : "r"(addr));
}
__device__ __forceinline__ void cpa16(unsigned dst, const void* src) {
    asm volatile("cp.async.cg.shared.global [%0], [%1], 16;" :: "r"(dst), "l"(src));
}
__device__ __forceinline__ float ex2(float x) {
    float y; asm("ex2.approx.ftz.f32 %0, %1;" : "=f"(y) : "f"(x)); return y;
}
// packed fp16 exp2: f32 subtract (precision), half2 pack, MUFU f16x2
__device__ __forceinline__ unsigned ex2_pk(float x0, float x1) {
    const __half2 h = __floats2half2_rn(x0, x1);
    unsigned y;
    asm("ex2.approx.f16x2 %0, %1;" : "=r"(y) : "r"(*reinterpret_cast<const unsigned*>(&h)));
    return y;
}

// ---------------------------------------------------------------------------
// Fused prologue (unchanged): fp16 Q_aug (0.125*log2e folded), fp16 K_aug,
// fp16 V, pre-weighted bias. Block = 64 t-rows of one head.
// ---------------------------------------------------------------------------
#define AP 68
__global__ __launch_bounds__(256) void aug_kernel(
    const float* __restrict__ Q, const float* __restrict__ K,
    const float* __restrict__ V, const float* __restrict__ d_bias,
    const float* __restrict__ W,
    const float* __restrict__ w_std, const float* __restrict__ w_rec,
    const float* __restrict__ w_disc)
{
    __shared__ float sW[PD * PR];
    __shared__ float sQ[64 * AP];
    __shared__ float sK[64 * AP];
    __shared__ float sLQ[64 * 16];
    __shared__ float sLK[64 * 16];

    const int tid = threadIdx.x;
    const int bh  = blockIdx.y;
    const int h   = bh % PH;
    const int t0  = blockIdx.x * 64;
    const size_t gbase = ((size_t)bh * PT + t0) * PD;

    for (int i = tid; i < PD * PR / 4; i += 256)
        *reinterpret_cast<float4*>(&sW[i * 4]) =
            reinterpret_cast<const float4*>(W)[i];
#pragma unroll
    for (int k = 0; k < 4; k++) {
        const int i = tid + k * 256;
        const int r = i >> 4, c4 = (i & 15) * 4;
        *reinterpret_cast<float4*>(&sQ[r * AP + c4]) =
            reinterpret_cast<const float4*>(Q + gbase)[i];
        *reinterpret_cast<float4*>(&sK[r * AP + c4]) =
            reinterpret_cast<const float4*>(K + gbase)[i];
    }
    __syncthreads();

    {
        const int r = tid >> 2, c4 = (tid & 3) * 4;
        float aq0 = 0.f, aq1 = 0.f, aq2 = 0.f, aq3 = 0.f;
        float ak0 = 0.f, ak1 = 0.f, ak2 = 0.f, ak3 = 0.f;
#pragma unroll
        for (int j = 0; j < PD; j++) {
            const float qv = sQ[r * AP + j];
            const float kv = sK[r * AP + j];
            const float4 wv = *reinterpret_cast<const float4*>(&sW[j * PR + c4]);
            aq0 = fmaf(qv, wv.x, aq0); aq1 = fmaf(qv, wv.y, aq1);
            aq2 = fmaf(qv, wv.z, aq2); aq3 = fmaf(qv, wv.w, aq3);
            ak0 = fmaf(kv, wv.x, ak0); ak1 = fmaf(kv, wv.y, ak1);
            ak2 = fmaf(kv, wv.z, ak2); ak3 = fmaf(kv, wv.w, ak3);
        }
        *reinterpret_cast<float4*>(&sLQ[r * 16 + c4]) = make_float4(aq0, aq1, aq2, aq3);
        *reinterpret_cast<float4*>(&sLK[r * 16 + c4]) = make_float4(ak0, ak1, ak2, ak3);
    }
    __syncthreads();

    {
        const float sstd = sqrtf(w_std[h]);
        const float srec = sqrtf(w_rec[h]);
        const float SCL = 0.125f * LOG2E;
        const int r = tid >> 2, d0 = (tid & 3) * 16;
        const size_t grow = gbase + (size_t)r * PD + d0;

        __half2 qo[8], ko[8], vo[8];
#pragma unroll
        for (int j = 0; j < 8; j++) {
            const int d = d0 + 2 * j;
            float q0, q1, k0, k1;
            if (d < PD_STD) {
                q0 = SCL * sstd * sQ[r * AP + d];   q1 = SCL * sstd * sQ[r * AP + d + 1];
                k0 = sstd * sK[r * AP + d];         k1 = sstd * sK[r * AP + d + 1];
            } else {
                const int rr = d - PD_STD;
                q0 = SCL * srec * sLK[r * 16 + rr]; q1 = SCL * srec * sLK[r * 16 + rr + 1];
                k0 = srec * sLQ[r * 16 + rr];       k1 = srec * sLQ[r * 16 + rr + 1];
            }
            qo[j] = __floats2half2_rn(q0, q1);
            ko[j] = __floats2half2_rn(k0, k1);
        }
#pragma unroll
        for (int j4 = 0; j4 < 4; j4++) {
            const float4 vv = *reinterpret_cast<const float4*>(&V[grow + 4 * j4]);
            vo[2 * j4]     = __floats2half2_rn(vv.x, vv.y);
            vo[2 * j4 + 1] = __floats2half2_rn(vv.z, vv.w);
        }
        *reinterpret_cast<uint4*>(&g_Qh[grow])     = *reinterpret_cast<uint4*>(&qo[0]);
        *reinterpret_cast<uint4*>(&g_Qh[grow + 8]) = *reinterpret_cast<uint4*>(&qo[4]);
        *reinterpret_cast<uint4*>(&g_Kh[grow])     = *reinterpret_cast<uint4*>(&ko[0]);
        *reinterpret_cast<uint4*>(&g_Kh[grow + 8]) = *reinterpret_cast<uint4*>(&ko[4]);
        *reinterpret_cast<uint4*>(&g_Vh[grow])     = *reinterpret_cast<uint4*>(&vo[0]);
        *reinterpret_cast<uint4*>(&g_Vh[grow + 8]) = *reinterpret_cast<uint4*>(&vo[4]);
        if (tid < 64)
            g_bw[(size_t)bh * PT + t0 + tid] =
                LOG2E * w_disc[h] * d_bias[(size_t)bh * PT + t0 + tid];
    }
}

// ---------------------------------------------------------------------------
// 128-key stage loader (SW128 xor swizzle) + f32 bias.
// ---------------------------------------------------------------------------
__device__ __forceinline__ void load_stage(unsigned sb, int stage,
                                           const __half* Kt, const __half* Vt,
                                           const float* bt, int tid)
{
    const unsigned kb = sb + (stage ? SK1 : SK0);
    const unsigned vb = sb + (stage ? SV1 : SV0);
    const unsigned bb = sb + (stage ? SB1 : SB0);
#pragma unroll
    for (int i = 0; i < 8; i++) {
        const int ch = tid + i * 128;
        const int r = ch >> 3, a = ch & 7;
        const unsigned off = (unsigned)(r * 128 + ((a ^ (r & 7)) << 4));
        cpa16(kb + off, Kt + r * 64 + a * 8);
        cpa16(vb + off, Vt + r * 64 + a * 8);
    }
    if (tid < 32) cpa16(bb + (unsigned)tid * 16u, bt + tid * 4);
    asm volatile("cp.async.commit_group;");
}

// ---------------------------------------------------------------------------
// Flash attention: HMMA.16816, 128-key tiles, distance-2 ldsm pipeline,
// bias injected as the C-operand of each nb's first QK mma, fp16-packed exp
// spread across PV, ones-column row sums. 128 threads, 3 CTA/SM.
// ---------------------------------------------------------------------------
__global__ __launch_bounds__(128, 3) void attn_kernel(float* __restrict__ out)
{
    extern __shared__ char sm[];
    const unsigned sb = (unsigned)__cvta_generic_to_shared(sm);

    const int bh = blockIdx.y;
    const int q_tile = (PT / QT - 1) - blockIdx.x;   // heavy tiles first
    const int nkt = q_tile / 2 + 1;                  // 128-key tiles
    const size_t base = (size_t)bh * PT * PD;
    const __half* Kg = g_Kh + base;
    const __half* Vg = g_Vh + base;
    const float*  bg = g_bw + (size_t)bh * PT;

    const int tid = threadIdx.x;
    const int w = tid >> 5, lane = tid & 31;
    const int g = lane >> 2, c = lane & 3;

    // fragment row/atom components
    const int kr  = 8 * (lane >> 4) + (lane & 7);                 // K rows (B frag)
    const int kao = (lane >> 3) & 1;
    const int qr  = 16 * w + 8 * ((lane >> 3) & 1) + (lane & 7);  // Q rows (A frag)
    const int qao = lane >> 4;
    const int vro = 8 * ((lane >> 3) & 1) + (lane & 7);           // V rows (trans B)
    const int vao = lane >> 4;
    const int qsw = qr & 7, ksw = kr & 7, vsw = vro & 7;
    const int grow0 = q_tile * QT + 16 * w + g;      // this lane's first q row

    // loop-invariant swizzled column offsets
    unsigned colK[4], colQ[4], colV[4];
#pragma unroll
    for (int kk = 0; kk < 4; kk++) {
        colK[kk] = (unsigned)(((2 * kk + kao) ^ ksw) << 4);
        colQ[kk] = (unsigned)(((2 * kk + qao) ^ qsw) << 4);
        colV[kk] = (unsigned)(((2 * kk + vao) ^ vsw) << 4);
    }
    const unsigned qbase2 = sb + SQ + (unsigned)qr * 128u;

    // stage0 K/V/bias + Q tile
    load_stage(sb, 0, Kg, Vg, bg, tid);
    {
        const __half* Qt = g_Qh + base + (size_t)q_tile * QT * PD;
#pragma unroll
        for (int i = 0; i < 4; i++) {
            const int ch = tid + i * 128;
            const int r = ch >> 3, a = ch & 7;
            cpa16(sb + SQ + (unsigned)(r * 128 + ((a ^ (r & 7)) << 4)), Qt + r * 64 + a * 8);
        }
        asm volatile("cp.async.commit_group;");
    }
    asm volatile("cp.async.wait_group 0;");
    __syncthreads();

    float acc[8][4];
#pragma unroll
    for (int nb = 0; nb < 8; nb++)
#pragma unroll
        for (int j = 0; j < 4; j++) acc[nb][j] = 0.f;
    float accl[4] = {0.f, 0.f, 0.f, 0.f};            // P row sums (ones-column mma)
    float m0 = -1e30f, m1 = -1e30f;

    int stage = 0;
    for (int kt = 0; kt < nkt; kt++) {
        if (kt) {
            asm volatile("cp.async.wait_group 0;");
            __syncthreads();
        }
        if (kt + 1 < nkt)
            load_stage(sb, stage ^ 1, Kg + (size_t)(kt + 1) * KT * PD,
                       Vg + (size_t)(kt + 1) * KT * PD, bg + (kt + 1) * KT, tid);

        const unsigned kb2 = sb + (stage ? SK1 : SK0) + (unsigned)kr * 128u;
        const unsigned vb2 = sb + (stage ? SV1 : SV0) + (unsigned)vro * 128u;
        const float* sB = (const float*)(sm + (stage ? SB1 : SB0));

        // ---- S (16x128 per warp): bias enters as first-mma C operand ----
        float s[16][4];

        // flattened 32-step (ldsm -> 2 mma) stream, distance-2 K ring,
        // Q fragments for kk loaded one kk ahead (parity buffer)
        {
            unsigned ring[3][4];
            unsigned qfb[2][4];
            ldsm4(qfb[0][0], qfb[0][1], qfb[0][2], qfb[0][3], qbase2 + colQ[0]);
            ldsm4(ring[0][0], ring[0][1], ring[0][2], ring[0][3], kb2 + colK[0]);
            ldsm4(ring[1][0], ring[1][1], ring[1][2], ring[1][3], kb2 + colK[0] + 2048u);
#pragma unroll
            for (int kk = 0; kk < 4; kk++) {
#pragma unroll
                for (int A2 = 0; A2 < 8; A2++) {
                    const int idx = kk * 8 + A2;
                    if (idx + 2 < 32) {
                        const int pkk = (idx + 2) >> 3, pA2 = (idx + 2) & 7;
                        unsigned* d = ring[(idx + 2) % 3];
                        ldsm4(d[0], d[1], d[2], d[3],
                              kb2 + colK[pkk] + (unsigned)(pA2 * 2048));
                    }
                    if (A2 == 4 && kk < 3) {
                        unsigned* qd = qfb[(kk + 1) & 1];
                        ldsm4(qd[0], qd[1], qd[2], qd[3], qbase2 + colQ[kk + 1]);
                    }
                    const unsigned* b = ring[idx % 3];
                    const unsigned* qa = qfb[kk & 1];
                    if (kk == 0) {   // first contribution: C = rank-1 bias
                        const float2 bbA =
                            *reinterpret_cast<const float2*>(sB + 8 * (2 * A2) + 2 * c);
                        const float2 bbB =
                            *reinterpret_cast<const float2*>(sB + 8 * (2 * A2 + 1) + 2 * c);
                        mma16816_init(s[2*A2][0], s[2*A2][1], s[2*A2][2], s[2*A2][3],
                                      qa[0], qa[1], qa[2], qa[3], b[0], b[1],
                                      bbA.x, bbA.y);
                        mma16816_init(s[2*A2+1][0], s[2*A2+1][1], s[2*A2+1][2], s[2*A2+1][3],
                                      qa[0], qa[1], qa[2], qa[3], b[2], b[3],
                                      bbB.x, bbB.y);
                    } else {
                        mma16816(s[2*A2][0], s[2*A2][1], s[2*A2][2], s[2*A2][3],
                                 qa[0], qa[1], qa[2], qa[3], b[0], b[1]);
                        mma16816(s[2*A2+1][0], s[2*A2+1][1], s[2*A2+1][2], s[2*A2+1][3],
                                 qa[0], qa[1], qa[2], qa[3], b[2], b[3]);
                    }
                }
            }
        }

        if (kt == nkt - 1) {   // causal mask, last 128-key tile
            const int kk0 = grow0 - kt * KT;
#pragma unroll
            for (int nb = 0; nb < 16; nb++) {
                const int j0 = 8 * nb + 2 * c, j1 = j0 + 1;
                if (j0 > kk0)     s[nb][0] = -1e30f;
                if (j1 > kk0)     s[nb][1] = -1e30f;
                if (j0 > kk0 + 8) s[nb][2] = -1e30f;
                if (j1 > kk0 + 8) s[nb][3] = -1e30f;
            }
        }

        // ---- row max over 128 keys (f32) ----
        float rm0 = fmaxf(s[0][0], s[0][1]), rm1 = fmaxf(s[0][2], s[0][3]);
#pragma unroll
        for (int nb = 1; nb < 16; nb++) {
            rm0 = fmaxf(rm0, fmaxf(s[nb][0], s[nb][1]));
            rm1 = fmaxf(rm1, fmaxf(s[nb][2], s[nb][3]));
        }
        rm0 = fmaxf(rm0, __shfl_xor_sync(0xffffffffu, rm0, 1));
        rm0 = fmaxf(rm0, __shfl_xor_sync(0xffffffffu, rm0, 2));
        rm1 = fmaxf(rm1, __shfl_xor_sync(0xffffffffu, rm1, 1));
        rm1 = fmaxf(rm1, __shfl_xor_sync(0xffffffffu, rm1, 2));
        const float mn0 = fmaxf(m0, rm0), mn1 = fmaxf(m1, rm1);
        const float co0 = ex2(m0 - mn0), co1 = ex2(m1 - mn1);
        const bool moved = (mn0 > m0) | (mn1 > m1);
        m0 = mn0; m1 = mn1;

        if (__ballot_sync(0xffffffffu, moved)) {     // skip rescale when max stable
#pragma unroll
            for (int nb = 0; nb < 8; nb++) {
                acc[nb][0] *= co0; acc[nb][1] *= co0;
                acc[nb][2] *= co1; acc[nb][3] *= co1;
            }
            accl[0] *= co0; accl[1] *= co0;
            accl[2] *= co1; accl[3] *= co1;
        }

        // ---- PV: flattened 32-step stream, distance-2 V ring, exp for kk+1
        //      spread across kk's steps, ones-column row-sum mma per kk ----
        {
            const unsigned ONES = 0x3C003C00u;
            unsigned ring[3][4];
            unsigned af[2][4];
            af[0][0] = ex2_pk(s[0][0] - mn0, s[0][1] - mn0);
            af[0][1] = ex2_pk(s[0][2] - mn1, s[0][3] - mn1);
            af[0][2] = ex2_pk(s[1][0] - mn0, s[1][1] - mn0);
            af[0][3] = ex2_pk(s[1][2] - mn1, s[1][3] - mn1);
            ldsm4t(ring[0][0], ring[0][1], ring[0][2], ring[0][3], vb2 + colV[0]);
            ldsm4t(ring[1][0], ring[1][1], ring[1][2], ring[1][3], vb2 + colV[1]);
#pragma unroll
            for (int kk = 0; kk < 8; kk++) {
#pragma unroll
                for (int A2 = 0; A2 < 4; A2++) {
                    const int idx = kk * 4 + A2;
                    if (idx + 2 < 32) {
                        const int pkk = (idx + 2) >> 2, pA2 = (idx + 2) & 3;
                        unsigned* d = ring[(idx + 2) % 3];
                        ldsm4t(d[0], d[1], d[2], d[3],
                               vb2 + (unsigned)(pkk * 2048) + colV[pA2]);
                    }
                    if (kk < 7) {   // one exp component per step for kk+1
                        unsigned* an = af[(kk + 1) & 1];
                        if (A2 == 0) an[0] = ex2_pk(s[2*kk+2][0] - mn0, s[2*kk+2][1] - mn0);
                        if (A2 == 1) an[1] = ex2_pk(s[2*kk+2][2] - mn1, s[2*kk+2][3] - mn1);
                        if (A2 == 2) an[2] = ex2_pk(s[2*kk+3][0] - mn0, s[2*kk+3][1] - mn0);
                        if (A2 == 3) an[3] = ex2_pk(s[2*kk+3][2] - mn1, s[2*kk+3][3] - mn1);
                    }
                    const unsigned* b = ring[idx % 3];
                    const unsigned* aa = af[kk & 1];
                    mma16816(acc[2*A2][0], acc[2*A2][1], acc[2*A2][2], acc[2*A2][3],
                             aa[0], aa[1], aa[2], aa[3], b[0], b[1]);
                    mma16816(acc[2*A2+1][0], acc[2*A2+1][1], acc[2*A2+1][2], acc[2*A2+1][3],
                             aa[0], aa[1], aa[2], aa[3], b[2], b[3]);
                }
                const unsigned* aa = af[kk & 1];
                mma16816(accl[0], accl[1], accl[2], accl[3],
                         aa[0], aa[1], aa[2], aa[3], ONES, ONES);
            }
        }
        stage ^= 1;
    }

    // ---- normalize + write (accl[0]=row g sum, accl[2]=row g+8 sum) ----
    const float inv0 = 1.0f / accl[0], inv1 = 1.0f / accl[2];
    float* og = out + base + ((size_t)q_tile * QT + 16 * w) * PD;
#pragma unroll
    for (int nb = 0; nb < 8; nb++) {
        *reinterpret_cast<float2*>(og + g * 64 + 8 * nb + 2 * c) =
            make_float2(acc[nb][0] * inv0, acc[nb][1] * inv0);
        *reinterpret_cast<float2*>(og + (g + 8) * 64 + 8 * nb + 2 * c) =
            make_float2(acc[nb][2] * inv1, acc[nb][3] * inv1);
    }
}

// ---------------------------------------------------------------------------
extern "C" void kernel_launch(void* const* d_in, const int* in_sizes, int n_in,
                              void* d_out, int out_size)
{
    const float* Q      = (const float*)d_in[0];
    const float* K      = (const float*)d_in[1];
    const float* V      = (const float*)d_in[2];
    const float* d_bias = (const float*)d_in[3];
    const float* W      = (const float*)d_in[4];
    const float* w_std  = (const float*)d_in[5];
    const float* w_rec  = (const float*)d_in[6];
    const float* w_disc = (const float*)d_in[7];
    float* out = (float*)d_out;

    cudaFuncSetAttribute(attn_kernel, cudaFuncAttributeMaxDynamicSharedMemorySize,
                         SMEM_BYTES);

    dim3 ag(PT / 64, PBH);
    aug_kernel<<<ag, 256>>>(Q, K, V, d_bias, W, w_std, w_rec, w_disc);

    dim3 grid(PT / QT, PBH);
    attn_kernel<<<grid, 128, SMEM_BYTES>>>(out);
}

// round 12
// speedup vs baseline: 1.0521x; 1.0450x over previous
#include <cuda_runtime.h>
#include <cuda_fp16.h>
#include <cstdint>

#define PB 2
#define PH 12
#define PT 2048
#define PD 64
#define PR 16
#define PD_STD 48
#define PBH (PB * PH)
#define QT 64
#define KT 128
#define LOG2E 1.4426950408889634f

// smem byte offsets (attn)
#define SQ  0
#define SK0 8192
#define SK1 24576
#define SV0 40960
#define SV1 57344
#define SB0 73728
#define SB1 74240
#define SMEM_BYTES 74752

__device__ __half g_Qh[PBH * PT * PD];
__device__ __half g_Kh[PBH * PT * PD];
__device__ __half g_Vh[PBH * PT * PD];
__device__ float  g_bw[PBH * PT];

__device__ __forceinline__ void mma16816(float& d0, float& d1, float& d2, float& d3,
                                         unsigned a0, unsigned a1, unsigned a2, unsigned a3,
                                         unsigned b0, unsigned b1) {
    asm volatile(
        "mma.sync.aligned.m16n8k16.row.col.f32.f16.f16.f32 "
        "{%0,%1,%2,%3},{%4,%5,%6,%7},{%8,%9},{%0,%1,%2,%3};"
        : "+f"(d0), "+f"(d1), "+f"(d2), "+f"(d3)
        : "r"(a0), "r"(a1), "r"(a2), "r"(a3), "r"(b0), "r"(b1));
}
__device__ __forceinline__ void mma16816_init(float& d0, float& d1, float& d2, float& d3,
                                              unsigned a0, unsigned a1, unsigned a2, unsigned a3,
                                              unsigned b0, unsigned b1, float c0, float c1) {
    asm volatile(
        "mma.sync.aligned.m16n8k16.row.col.f32.f16.f16.f32 "
        "{%0,%1,%2,%3},{%4,%5,%6,%7},{%8,%9},{%10,%11,%10,%11};"
        : "=f"(d0), "=f"(d1), "=f"(d2), "=f"(d3)
        : "r"(a0), "r"(a1), "r"(a2), "r"(a3), "r"(b0), "r"(b1),
          "f"(c0), "f"(c1));
}
__device__ __forceinline__ void ldsm4(unsigned& r0, unsigned& r1, unsigned& r2, unsigned& r3,
                                      unsigned addr) {
    asm volatile("ldmatrix.sync.aligned.m8n8.x4.shared.b16 {%0,%1,%2,%3}, [%4];"
                 : "=r"(r0), "=r"(r1), "=r"(r2), "=r"(r3) : "r"(addr));
}
__device__ __forceinline__ void ldsm4t(unsigned& r0, unsigned& r1, unsigned& r2, unsigned& r3,
                                       unsigned addr) {
    asm volatile("ldmatrix.sync.aligned.m8n8.x4.trans.shared.b16 {%0,%1,%2,%3}, [%4];"
                 : "=r"(r0), "=r"(r1), "=r"(r2), "=r"(r3) : "r"(addr));
}
__device__ __forceinline__ void cpa16(unsigned dst, const void* src) {
    asm volatile("cp.async.cg.shared.global [%0], [%1], 16;" :: "r"(dst), "l"(src));
}
__device__ __forceinline__ float ex2(float x) {
    float y; asm("ex2.approx.ftz.f32 %0, %1;" : "=f"(y) : "f"(x)); return y;
}
__device__ __forceinline__ unsigned ex2_pk(float x0, float x1) {
    const __half2 h = __floats2half2_rn(x0, x1);
    unsigned y;
    asm("ex2.approx.f16x2 %0, %1;" : "=r"(y) : "r"(*reinterpret_cast<const unsigned*>(&h)));
    return y;
}

// ---------------------------------------------------------------------------
// Fused prologue, fp16 math: Q/K staged fp16, low-rank projection in HFMA2.
// Block = 64 t-rows of one head.
// ---------------------------------------------------------------------------
#define QPH 68   // sQh/sKh pitch in halves (136B rows: 8B aligned, bank-rotating)
#define WPH 66   // sWh pitch in halves
__global__ __launch_bounds__(256) void aug_kernel(
    const float* __restrict__ Q, const float* __restrict__ K,
    const float* __restrict__ V, const float* __restrict__ d_bias,
    const float* __restrict__ W,
    const float* __restrict__ w_std, const float* __restrict__ w_rec,
    const float* __restrict__ w_disc)
{
    __shared__ __half sWh[PR * WPH];       // [rj][j], transposed
    __shared__ __half sQh[64 * QPH];
    __shared__ __half sKh[64 * QPH];
    __shared__ float sLQ[64 * 16];
    __shared__ float sLK[64 * 16];

    const int tid = threadIdx.x;
    const int bh  = blockIdx.y;
    const int h   = bh % PH;
    const int t0  = blockIdx.x * 64;
    const size_t gbase = ((size_t)bh * PT + t0) * PD;

    // phase A: stage W (transposed fp16), Q, K (fp16)
    for (int idx = tid; idx < PD * PR; idx += 256) {
        const int rj = idx & 15, j = idx >> 4;
        sWh[rj * WPH + j] = __float2half_rn(W[j * PR + rj]);
    }
#pragma unroll
    for (int k = 0; k < 4; k++) {
        const int i = tid + k * 256;             // float4 index
        const int r = i >> 4, c4 = (i & 15) * 4;
        const float4 qv = reinterpret_cast<const float4*>(Q + gbase)[i];
        const float4 kv = reinterpret_cast<const float4*>(K + gbase)[i];
        __half2 qh[2] = {__floats2half2_rn(qv.x, qv.y), __floats2half2_rn(qv.z, qv.w)};
        __half2 kh[2] = {__floats2half2_rn(kv.x, kv.y), __floats2half2_rn(kv.z, kv.w)};
        *reinterpret_cast<uint2*>(&sQh[r * QPH + c4]) = *reinterpret_cast<uint2*>(qh);
        *reinterpret_cast<uint2*>(&sKh[r * QPH + c4]) = *reinterpret_cast<uint2*>(kh);
    }
    __syncthreads();

    // phase B: low-rank projections in packed fp16 (4 threads/row, 4 rj each)
    {
        const int r = tid >> 2, c4 = (tid & 3) * 4;
        __half2 aq[4], ak[4];
#pragma unroll
        for (int u = 0; u < 4; u++) { aq[u] = __half2(0, 0); ak[u] = __half2(0, 0); }
#pragma unroll
        for (int jp = 0; jp < 32; jp++) {
            const __half2 q2 = *reinterpret_cast<const __half2*>(&sQh[r * QPH + 2 * jp]);
            const __half2 k2 = *reinterpret_cast<const __half2*>(&sKh[r * QPH + 2 * jp]);
#pragma unroll
            for (int u = 0; u < 4; u++) {
                const __half2 w2 =
                    *reinterpret_cast<const __half2*>(&sWh[(c4 + u) * WPH + 2 * jp]);
                aq[u] = __hfma2(q2, w2, aq[u]);
                ak[u] = __hfma2(k2, w2, ak[u]);
            }
        }
#pragma unroll
        for (int u = 0; u < 4; u++) {
            sLQ[r * 16 + c4 + u] = __low2float(aq[u]) + __high2float(aq[u]);
            sLK[r * 16 + c4 + u] = __low2float(ak[u]) + __high2float(ak[u]);
        }
    }
    __syncthreads();

    // phase C: emit fp16 Q_aug / K_aug / V + bias
    {
        const float sstd = sqrtf(w_std[h]);
        const float srec = sqrtf(w_rec[h]);
        const float SCL = 0.125f * LOG2E;
        const int r = tid >> 2, d0 = (tid & 3) * 16;
        const size_t grow = gbase + (size_t)r * PD + d0;

        __half2 qo[8], ko[8], vo[8];
#pragma unroll
        for (int j = 0; j < 8; j++) {
            const int d = d0 + 2 * j;
            float q0, q1, k0, k1;
            if (d < PD_STD) {
                const __half2 qh = *reinterpret_cast<const __half2*>(&sQh[r * QPH + d]);
                const __half2 kh = *reinterpret_cast<const __half2*>(&sKh[r * QPH + d]);
                q0 = SCL * sstd * __low2float(qh);  q1 = SCL * sstd * __high2float(qh);
                k0 = sstd * __low2float(kh);        k1 = sstd * __high2float(kh);
            } else {
                const int rr = d - PD_STD;
                q0 = SCL * srec * sLK[r * 16 + rr]; q1 = SCL * srec * sLK[r * 16 + rr + 1];
                k0 = srec * sLQ[r * 16 + rr];       k1 = srec * sLQ[r * 16 + rr + 1];
            }
            qo[j] = __floats2half2_rn(q0, q1);
            ko[j] = __floats2half2_rn(k0, k1);
        }
#pragma unroll
        for (int j4 = 0; j4 < 4; j4++) {
            const float4 vv = *reinterpret_cast<const float4*>(&V[grow + 4 * j4]);
            vo[2 * j4]     = __floats2half2_rn(vv.x, vv.y);
            vo[2 * j4 + 1] = __floats2half2_rn(vv.z, vv.w);
        }
        *reinterpret_cast<uint4*>(&g_Qh[grow])     = *reinterpret_cast<uint4*>(&qo[0]);
        *reinterpret_cast<uint4*>(&g_Qh[grow + 8]) = *reinterpret_cast<uint4*>(&qo[4]);
        *reinterpret_cast<uint4*>(&g_Kh[grow])     = *reinterpret_cast<uint4*>(&ko[0]);
        *reinterpret_cast<uint4*>(&g_Kh[grow + 8]) = *reinterpret_cast<uint4*>(&ko[4]);
        *reinterpret_cast<uint4*>(&g_Vh[grow])     = *reinterpret_cast<uint4*>(&vo[0]);
        *reinterpret_cast<uint4*>(&g_Vh[grow + 8]) = *reinterpret_cast<uint4*>(&vo[4]);
        if (tid < 64)
            g_bw[(size_t)bh * PT + t0 + tid] =
                LOG2E * w_disc[h] * d_bias[(size_t)bh * PT + t0 + tid];
    }
}

// ---------------------------------------------------------------------------
// Stage loader; nch = number of 16-row chunks (4 = half tile, 8 = full).
// ---------------------------------------------------------------------------
__device__ __forceinline__ void load_stage(unsigned sb, int stage,
                                           const __half* Kt, const __half* Vt,
                                           const float* bt, int tid, int nch)
{
    const unsigned kb = sb + (stage ? SK1 : SK0);
    const unsigned vb = sb + (stage ? SV1 : SV0);
    const unsigned bb = sb + (stage ? SB1 : SB0);
#pragma unroll
    for (int i = 0; i < 8; i++) {
        if (i < nch) {
            const int ch = tid + i * 128;
            const int r = ch >> 3, a = ch & 7;
            const unsigned off = (unsigned)(r * 128 + ((a ^ (r & 7)) << 4));
            cpa16(kb + off, Kt + r * 64 + a * 8);
            cpa16(vb + off, Vt + r * 64 + a * 8);
        }
    }
    if (tid < 32) cpa16(bb + (unsigned)tid * 16u, bt + tid * 4);
    asm volatile("cp.async.commit_group;");
}

// ---------------------------------------------------------------------------
// Flash attention: HMMA.16816, 128-key tiles, distance-2 pipelines, bias in
// mma C-operand, fp16 exp in PV, ones-column row sums. Final tile split out
// and specialized (even q_tiles skip the fully-masked upper 64 keys).
// ---------------------------------------------------------------------------
__global__ __launch_bounds__(128, 3) void attn_kernel(float* __restrict__ out)
{
    extern __shared__ char sm[];
    const unsigned sb = (unsigned)__cvta_generic_to_shared(sm);

    const int bh = blockIdx.y;
    const int q_tile = (PT / QT - 1) - blockIdx.x;
    const int nkt = q_tile / 2 + 1;
    const int lastnch = (q_tile & 1) ? 8 : 4;
    const size_t base = (size_t)bh * PT * PD;
    const __half* Kg = g_Kh + base;
    const __half* Vg = g_Vh + base;
    const float*  bg = g_bw + (size_t)bh * PT;

    const int tid = threadIdx.x;
    const int w = tid >> 5, lane = tid & 31;
    const int g = lane >> 2, c = lane & 3;

    const int kr  = 8 * (lane >> 4) + (lane & 7);
    const int kao = (lane >> 3) & 1;
    const int qr  = 16 * w + 8 * ((lane >> 3) & 1) + (lane & 7);
    const int qao = lane >> 4;
    const int vro = 8 * ((lane >> 3) & 1) + (lane & 7);
    const int vao = lane >> 4;
    const int qsw = qr & 7, ksw = kr & 7, vsw = vro & 7;
    const int grow0 = q_tile * QT + 16 * w + g;

    unsigned colK[4], colQ[4], colV[4];
#pragma unroll
    for (int kk = 0; kk < 4; kk++) {
        colK[kk] = (unsigned)(((2 * kk + kao) ^ ksw) << 4);
        colQ[kk] = (unsigned)(((2 * kk + qao) ^ qsw) << 4);
        colV[kk] = (unsigned)(((2 * kk + vao) ^ vsw) << 4);
    }
    const unsigned qbase2 = sb + SQ + (unsigned)qr * 128u;

    load_stage(sb, 0, Kg, Vg, bg, tid, (nkt == 1) ? lastnch : 8);
    {
        const __half* Qt = g_Qh + base + (size_t)q_tile * QT * PD;
#pragma unroll
        for (int i = 0; i < 4; i++) {
            const int ch = tid + i * 128;
            const int r = ch >> 3, a = ch & 7;
            cpa16(sb + SQ + (unsigned)(r * 128 + ((a ^ (r & 7)) << 4)), Qt + r * 64 + a * 8);
        }
        asm volatile("cp.async.commit_group;");
    }
    asm volatile("cp.async.wait_group 0;");
    __syncthreads();

    float acc[8][4];
#pragma unroll
    for (int nb = 0; nb < 8; nb++)
#pragma unroll
        for (int j = 0; j < 4; j++) acc[nb][j] = 0.f;
    float accl[4] = {0.f, 0.f, 0.f, 0.f};
    float m0 = -1e30f, m1 = -1e30f;

    int stage = 0;
    // ======================= main loop: full, unmasked tiles ================
    for (int kt = 0; kt < nkt - 1; kt++) {
        if (kt) {
            asm volatile("cp.async.wait_group 0;");
            __syncthreads();
        }
        load_stage(sb, stage ^ 1, Kg + (size_t)(kt + 1) * KT * PD,
                   Vg + (size_t)(kt + 1) * KT * PD, bg + (kt + 1) * KT, tid,
                   (kt + 2 == nkt) ? lastnch : 8);

        const unsigned kb2 = sb + (stage ? SK1 : SK0) + (unsigned)kr * 128u;
        const unsigned vb2 = sb + (stage ? SV1 : SV0) + (unsigned)vro * 128u;
        const float* sB = (const float*)(sm + (stage ? SB1 : SB0));

        float s[16][4];
        {
            unsigned ring[3][4];
            unsigned qfb[2][4];
            ldsm4(qfb[0][0], qfb[0][1], qfb[0][2], qfb[0][3], qbase2 + colQ[0]);
            ldsm4(ring[0][0], ring[0][1], ring[0][2], ring[0][3], kb2 + colK[0]);
            ldsm4(ring[1][0], ring[1][1], ring[1][2], ring[1][3], kb2 + colK[0] + 2048u);
#pragma unroll
            for (int kk = 0; kk < 4; kk++) {
#pragma unroll
                for (int A2 = 0; A2 < 8; A2++) {
                    const int idx = kk * 8 + A2;
                    if (idx + 2 < 32) {
                        const int pkk = (idx + 2) >> 3, pA2 = (idx + 2) & 7;
                        unsigned* d = ring[(idx + 2) % 3];
                        ldsm4(d[0], d[1], d[2], d[3],
                              kb2 + colK[pkk] + (unsigned)(pA2 * 2048));
                    }
                    if (A2 == 4 && kk < 3) {
                        unsigned* qd = qfb[(kk + 1) & 1];
                        ldsm4(qd[0], qd[1], qd[2], qd[3], qbase2 + colQ[kk + 1]);
                    }
                    const unsigned* b = ring[idx % 3];
                    const unsigned* qa = qfb[kk & 1];
                    if (kk == 0) {
                        const float2 bbA =
                            *reinterpret_cast<const float2*>(sB + 8 * (2 * A2) + 2 * c);
                        const float2 bbB =
                            *reinterpret_cast<const float2*>(sB + 8 * (2 * A2 + 1) + 2 * c);
                        mma16816_init(s[2*A2][0], s[2*A2][1], s[2*A2][2], s[2*A2][3],
                                      qa[0], qa[1], qa[2], qa[3], b[0], b[1],
                                      bbA.x, bbA.y);
                        mma16816_init(s[2*A2+1][0], s[2*A2+1][1], s[2*A2+1][2], s[2*A2+1][3],
                                      qa[0], qa[1], qa[2], qa[3], b[2], b[3],
                                      bbB.x, bbB.y);
                    } else {
                        mma16816(s[2*A2][0], s[2*A2][1], s[2*A2][2], s[2*A2][3],
                                 qa[0], qa[1], qa[2], qa[3], b[0], b[1]);
                        mma16816(s[2*A2+1][0], s[2*A2+1][1], s[2*A2+1][2], s[2*A2+1][3],
                                 qa[0], qa[1], qa[2], qa[3], b[2], b[3]);
                    }
                }
            }
        }

        float rm0 = fmaxf(s[0][0], s[0][1]), rm1 = fmaxf(s[0][2], s[0][3]);
#pragma unroll
        for (int nb = 1; nb < 16; nb++) {
            rm0 = fmaxf(rm0, fmaxf(s[nb][0], s[nb][1]));
            rm1 = fmaxf(rm1, fmaxf(s[nb][2], s[nb][3]));
        }
        rm0 = fmaxf(rm0, __shfl_xor_sync(0xffffffffu, rm0, 1));
        rm0 = fmaxf(rm0, __shfl_xor_sync(0xffffffffu, rm0, 2));
        rm1 = fmaxf(rm1, __shfl_xor_sync(0xffffffffu, rm1, 1));
        rm1 = fmaxf(rm1, __shfl_xor_sync(0xffffffffu, rm1, 2));
        const float mn0 = fmaxf(m0, rm0), mn1 = fmaxf(m1, rm1);
        const float co0 = ex2(m0 - mn0), co1 = ex2(m1 - mn1);
        const bool moved = (mn0 > m0) | (mn1 > m1);
        m0 = mn0; m1 = mn1;

        if (__ballot_sync(0xffffffffu, moved)) {
#pragma unroll
            for (int nb = 0; nb < 8; nb++) {
                acc[nb][0] *= co0; acc[nb][1] *= co0;
                acc[nb][2] *= co1; acc[nb][3] *= co1;
            }
            accl[0] *= co0; accl[1] *= co0;
            accl[2] *= co1; accl[3] *= co1;
        }

        {
            const unsigned ONES = 0x3C003C00u;
            unsigned ring[3][4];
            unsigned af[2][4];
            af[0][0] = ex2_pk(s[0][0] - mn0, s[0][1] - mn0);
            af[0][1] = ex2_pk(s[0][2] - mn1, s[0][3] - mn1);
            af[0][2] = ex2_pk(s[1][0] - mn0, s[1][1] - mn0);
            af[0][3] = ex2_pk(s[1][2] - mn1, s[1][3] - mn1);
            ldsm4t(ring[0][0], ring[0][1], ring[0][2], ring[0][3], vb2 + colV[0]);
            ldsm4t(ring[1][0], ring[1][1], ring[1][2], ring[1][3], vb2 + colV[1]);
#pragma unroll
            for (int kk = 0; kk < 8; kk++) {
#pragma unroll
                for (int A2 = 0; A2 < 4; A2++) {
                    const int idx = kk * 4 + A2;
                    if (idx + 2 < 32) {
                        const int pkk = (idx + 2) >> 2, pA2 = (idx + 2) & 3;
                        unsigned* d = ring[(idx + 2) % 3];
                        ldsm4t(d[0], d[1], d[2], d[3],
                               vb2 + (unsigned)(pkk * 2048) + colV[pA2]);
                    }
                    if (kk < 7) {
                        unsigned* an = af[(kk + 1) & 1];
                        if (A2 == 0) an[0] = ex2_pk(s[2*kk+2][0] - mn0, s[2*kk+2][1] - mn0);
                        if (A2 == 1) an[1] = ex2_pk(s[2*kk+2][2] - mn1, s[2*kk+2][3] - mn1);
                        if (A2 == 2) an[2] = ex2_pk(s[2*kk+3][0] - mn0, s[2*kk+3][1] - mn0);
                        if (A2 == 3) an[3] = ex2_pk(s[2*kk+3][2] - mn1, s[2*kk+3][3] - mn1);
                    }
                    const unsigned* b = ring[idx % 3];
                    const unsigned* aa = af[kk & 1];
                    mma16816(acc[2*A2][0], acc[2*A2][1], acc[2*A2][2], acc[2*A2][3],
                             aa[0], aa[1], aa[2], aa[3], b[0], b[1]);
                    mma16816(acc[2*A2+1][0], acc[2*A2+1][1], acc[2*A2+1][2], acc[2*A2+1][3],
                             aa[0], aa[1], aa[2], aa[3], b[2], b[3]);
                }
                const unsigned* aa = af[kk & 1];
                mma16816(accl[0], accl[1], accl[2], accl[3],
                         aa[0], aa[1], aa[2], aa[3], ONES, ONES);
            }
        }
        stage ^= 1;
    }

    // ======================= final tile (masked; NA2=4 for even q_tile) ====
    if (nkt > 1) {
        asm volatile("cp.async.wait_group 0;");
        __syncthreads();
    }
    {
        const unsigned kb2 = sb + (stage ? SK1 : SK0) + (unsigned)kr * 128u;
        const unsigned vb2 = sb + (stage ? SV1 : SV0) + (unsigned)vro * 128u;
        const float* sB = (const float*)(sm + (stage ? SB1 : SB0));
        const int kk0 = grow0 - (nkt - 1) * KT;   // causal bound for row g

#define FINAL_TILE(NA2)                                                          \
        {                                                                        \
            float s[2 * NA2][4];                                                 \
            _Pragma("unroll")                                                    \
            for (int kk = 0; kk < 4; kk++) {                                     \
                unsigned qa0, qa1, qa2, qa3;                                     \
                ldsm4(qa0, qa1, qa2, qa3, qbase2 + colQ[kk]);                    \
                _Pragma("unroll")                                                \
                for (int A2 = 0; A2 < NA2; A2++) {                               \
                    unsigned b0, b1, b2, b3;                                     \
                    ldsm4(b0, b1, b2, b3,                                        \
                          kb2 + colK[kk] + (unsigned)(A2 * 2048));               \
                    if (kk == 0) {                                               \
                        const float2 bbA = *reinterpret_cast<const float2*>(     \
                            sB + 8 * (2 * A2) + 2 * c);                          \
                        const float2 bbB = *reinterpret_cast<const float2*>(     \
                            sB + 8 * (2 * A2 + 1) + 2 * c);                      \
                        mma16816_init(s[2*A2][0], s[2*A2][1], s[2*A2][2],        \
                                      s[2*A2][3], qa0, qa1, qa2, qa3, b0, b1,    \
                                      bbA.x, bbA.y);                             \
                        mma16816_init(s[2*A2+1][0], s[2*A2+1][1], s[2*A2+1][2],  \
                                      s[2*A2+1][3], qa0, qa1, qa2, qa3, b2, b3,  \
                                      bbB.x, bbB.y);                             \
                    } else {                                                     \
                        mma16816(s[2*A2][0], s[2*A2][1], s[2*A2][2], s[2*A2][3], \
                                 qa0, qa1, qa2, qa3, b0, b1);                    \
                        mma16816(s[2*A2+1][0], s[2*A2+1][1], s[2*A2+1][2],       \
                                 s[2*A2+1][3], qa0, qa1, qa2, qa3, b2, b3);      \
                    }                                                            \
                }                                                                \
            }                                                                    \
            _Pragma("unroll")                                                    \
            for (int nb = 0; nb < 2 * NA2; nb++) {                               \
                const int j0 = 8 * nb + 2 * c, j1 = j0 + 1;                      \
                if (j0 > kk0)     s[nb][0] = -1e30f;                             \
                if (j1 > kk0)     s[nb][1] = -1e30f;                             \
                if (j0 > kk0 + 8) s[nb][2] = -1e30f;                             \
                if (j1 > kk0 + 8) s[nb][3] = -1e30f;                             \
            }                                                                    \
            float rm0 = fmaxf(s[0][0], s[0][1]), rm1 = fmaxf(s[0][2], s[0][3]);  \
            _Pragma("unroll")                                                    \
            for (int nb = 1; nb < 2 * NA2; nb++) {                               \
                rm0 = fmaxf(rm0, fmaxf(s[nb][0], s[nb][1]));                     \
                rm1 = fmaxf(rm1, fmaxf(s[nb][2], s[nb][3]));                     \
            }                                                                    \
            rm0 = fmaxf(rm0, __shfl_xor_sync(0xffffffffu, rm0, 1));              \
            rm0 = fmaxf(rm0, __shfl_xor_sync(0xffffffffu, rm0, 2));              \
            rm1 = fmaxf(rm1, __shfl_xor_sync(0xffffffffu, rm1, 1));              \
            rm1 = fmaxf(rm1, __shfl_xor_sync(0xffffffffu, rm1, 2));              \
            const float mn0 = fmaxf(m0, rm0), mn1 = fmaxf(m1, rm1);              \
            const float co0 = ex2(m0 - mn0), co1 = ex2(m1 - mn1);                \
            _Pragma("unroll")                                                    \
            for (int nb = 0; nb < 8; nb++) {                                     \
                acc[nb][0] *= co0; acc[nb][1] *= co0;                            \
                acc[nb][2] *= co1; acc[nb][3] *= co1;                            \
            }                                                                    \
            accl[0] *= co0; accl[1] *= co0;                                      \
            accl[2] *= co1; accl[3] *= co1;                                      \
            const unsigned ONES = 0x3C003C00u;                                   \
            _Pragma("unroll")                                                    \
            for (int kk = 0; kk < NA2; kk++) {                                   \
                const unsigned a0 = ex2_pk(s[2*kk][0] - mn0, s[2*kk][1] - mn0);  \
                const unsigned a1 = ex2_pk(s[2*kk][2] - mn1, s[2*kk][3] - mn1);  \
                const unsigned a2 = ex2_pk(s[2*kk+1][0] - mn0,                   \
                                           s[2*kk+1][1] - mn0);                  \
                const unsigned a3 = ex2_pk(s[2*kk+1][2] - mn1,                   \
                                           s[2*kk+1][3] - mn1);                  \
                _Pragma("unroll")                                                \
                for (int A2 = 0; A2 < 4; A2++) {                                 \
                    unsigned b0, b1, b2, b3;                                     \
                    ldsm4t(b0, b1, b2, b3,                                       \
                           vb2 + (unsigned)(kk * 2048) + colV[A2]);              \
                    mma16816(acc[2*A2][0], acc[2*A2][1], acc[2*A2][2],           \
                             acc[2*A2][3], a0, a1, a2, a3, b0, b1);              \
                    mma16816(acc[2*A2+1][0], acc[2*A2+1][1], acc[2*A2+1][2],     \
                             acc[2*A2+1][3], a0, a1, a2, a3, b2, b3);            \
                }                                                                \
                mma16816(accl[0], accl[1], accl[2], accl[3],                     \
                         a0, a1, a2, a3, ONES, ONES);                            \
            }                                                                    \
        }

        if (q_tile & 1) FINAL_TILE(8) else FINAL_TILE(4)
#undef FINAL_TILE
    }

    // ---- normalize + write ----
    const float inv0 = 1.0f / accl[0], inv1 = 1.0f / accl[2];
    float* og = out + base + ((size_t)q_tile * QT + 16 * w) * PD;
#pragma unroll
    for (int nb = 0; nb < 8; nb++) {
        *reinterpret_cast<float2*>(og + g * 64 + 8 * nb + 2 * c) =
            make_float2(acc[nb][0] * inv0, acc[nb][1] * inv0);
        *reinterpret_cast<float2*>(og + (g + 8) * 64 + 8 * nb + 2 * c) =
            make_float2(acc[nb][2] * inv1, acc[nb][3] * inv1);
    }
}

// ---------------------------------------------------------------------------
extern "C" void kernel_launch(void* const* d_in, const int* in_sizes, int n_in,
                              void* d_out, int out_size)
{
    const float* Q      = (const float*)d_in[0];
    const float* K      = (const float*)d_in[1];
    const float* V      = (const float*)d_in[2];
    const float* d_bias = (const float*)d_in[3];
    const float* W      = (const float*)d_in[4];
    const float* w_std  = (const float*)d_in[5];
    const float* w_rec  = (const float*)d_in[6];
    const float* w_disc = (const float*)d_in[7];
    float* out = (float*)d_out;

    cudaFuncSetAttribute(attn_kernel, cudaFuncAttributeMaxDynamicSharedMemorySize,
                         SMEM_BYTES);

    dim3 ag(PT / 64, PBH);
    aug_kernel<<<ag, 256>>>(Q, K, V, d_bias, W, w_std, w_rec, w_disc);

    dim3 grid(PT / QT, PBH);
    attn_kernel<<<grid, 128, SMEM_BYTES>>>(out);
}